// round 11
// baseline (speedup 1.0000x reference)
#include <cuda_runtime.h>
#include <string.h>

// ---------------------------------------------------------------------------
// GraphFeatureTokenizer fused kernel for GB300 (sm_103a) — Round 10
//
// Base structure = R3 (best, 307.7us): NSPLIT=3 x 256 cols, TM=8, same-tile
// L2 prefetch, __stcs output, fma.rn.f32x2 GEMM, 24 warps/SM.
// R10: eliminate the ~512 pack-MOVs per warp-tile (R5's idea) WITHOUT the
// TM=4 smem regression: TPB=384 with 2 CTAs/SM keeps 24 warps/SM while
// raising smem/CTA to 114KB, making room for pre-duplicated ie
// ((x,x) float2 pairs). Layout stride = 132 floats/token (528B) so phase-A
// STS.128 banks are 4m mod 32 -> conflict-free; GEMM multipliers come from
// broadcast LDS.128 directly (zero MOVs). GEMM issue slots/warp-tile:
// ~1728 -> ~1344 (-22%).
// ---------------------------------------------------------------------------

#define HID      768
#define HID4     192              // float4 per row
#define NSPLIT   3
#define SCOLS4   64               // float4 cols per split
#define MAXLEN   15360
#define NB       8
#define SLOTS    (NB * MAXLEN)    // 122880
#define TM       8
#define NTILES   (SLOTS / TM)     // 15360
#define TPB      384
#define NGRP     6                // 6 groups of 64 threads
#define GSZ      64
#define NWORK    101              // 2 CTAs/SM * 152 SMs ~ 303 = 3*101

#define F_ELEMS  (SLOTS * HID)    // 94371840
#define M_ELEMS  (SLOTS)          // 122880
#define I_ELEMS  (SLOTS * 2)      // 245760

#define IESTRIDE 132              // dup-floats per token (128 + 4 pad; 528B)
#define SM_W_FLOATS   (64 * 256)                    // 16384 floats = 64KB
#define SM_IED_FLOATS (NGRP * TM * IESTRIDE)        // 6336 floats = 24.75KB
#define SM_META_INTS  (NGRP * TM * 5)               // 240
#define SM_OFF_INTS   32
#define SMEM_BYTES    ((SM_W_FLOATS + SM_IED_FLOATS) * 4 + (SM_META_INTS + SM_OFF_INTS) * 4)

typedef unsigned long long ull;

__device__ __forceinline__ float2 unpack2(ull v) {
    float2 r; memcpy(&r, &v, 8);
    return r;
}
__device__ __forceinline__ ull lo2(float4 w) {
    float2 q = make_float2(w.x, w.y);
    ull r; memcpy(&r, &q, 8);
    return r;
}
__device__ __forceinline__ ull hi2(float4 w) {
    float2 q = make_float2(w.z, w.w);
    ull r; memcpy(&r, &q, 8);
    return r;
}
__device__ __forceinline__ void fma2(ull& acc, ull a, ull b) {
    asm("fma.rn.f32x2 %0, %1, %2, %0;" : "+l"(acc) : "l"(a), "l"(b));
}
__device__ __forceinline__ void pf_l2(const void* p) {
    asm volatile("prefetch.global.L2 [%0];" :: "l"(p));
}

extern "C" __global__ void __launch_bounds__(TPB, 2)
gft_kernel(const float* __restrict__ embedW,
           const float* __restrict__ lapW,
           const float* __restrict__ orderW,
           const float* __restrict__ eig,
           const int*   __restrict__ nodeData,
           const int*   __restrict__ edgeData,
           const int*   __restrict__ edgeIndex,
           const int*   __restrict__ nodeNum,
           const int*   __restrict__ edgeNum,
           float*       __restrict__ out,
           int Etot, int extraMode)
{
    extern __shared__ float smem[];
    float4* sW4   = (float4*)smem;                        // [64 k][64 c4]
    float*  sIED  = smem + SM_W_FLOATS;                   // [NGRP][TM][IESTRIDE]
    int*    sMeta = (int*)(sIED + SM_IED_FLOATS);         // [NGRP][TM][5]
    int*    sOff  = sMeta + SM_META_INTS;                 // [32]

    const int tid    = threadIdx.x;
    const int nwork  = gridDim.x / NSPLIT;
    const int split  = blockIdx.x / nwork;                // 0..2
    const int worker = blockIdx.x - split * nwork;

    // --- init: weight slice -> smem, prefix sums ---
    {
        const float4* s = (const float4*)lapW;
        #pragma unroll 4
        for (int i = tid; i < 64 * SCOLS4; i += TPB) {
            const int k = i >> 6, c4 = i & 63;
            sW4[i] = s[k * HID4 + split * SCOLS4 + c4];
        }
    }
    if (tid < NB) {
        int no = 0, eo = 0;
        for (int x = 0; x < tid; x++) { no += nodeNum[x]; eo += edgeNum[x]; }
        sOff[tid]      = no;
        sOff[8 + tid]  = eo;
        sOff[16 + tid] = nodeNum[tid];
        sOff[24 + tid] = nodeNum[tid] + edgeNum[tid];
    }
    __syncthreads();

    const int g  = tid >> 6;                 // group 0..5
    const int lt = tid & 63;
    float* gIED  = sIED + g * TM * IESTRIDE;
    int*   gMeta = sMeta + g * TM * 5;
    const int barid = 1 + g;                 // named barriers 1..6
    const int grp   = worker * NGRP + g;
    const int ngrp  = nwork * NGRP;
    const int cb4   = split * SCOLS4 + lt;   // thread's float4 col

    for (int tile = grp; tile < NTILES; tile += ngrp) {
        const int slot0 = tile * TM;
        const int b  = slot0 / MAXLEN;
        const int t0 = slot0 - b * MAXLEN;
        const int nOff = sOff[b], eOff = sOff[8 + b];
        const int nn = sOff[16 + b], seq = sOff[24 + b];

        if (t0 >= seq) {
            if (split == 0 && lt < TM && extraMode) {
                const int slot = slot0 + lt;
                if (extraMode == 1) {
                    out[(size_t)F_ELEMS + slot] = 1.0f;
                    out[(size_t)F_ELEMS + M_ELEMS + 2 * slot]     = 0.0f;
                    out[(size_t)F_ELEMS + M_ELEMS + 2 * slot + 1] = 0.0f;
                } else {
                    ((unsigned char*)out)[(size_t)F_ELEMS * 4 + slot] = 1;
                    int* ip = (int*)((char*)out + (size_t)F_ELEMS * 4 + M_ELEMS);
                    ip[2 * slot] = 0; ip[2 * slot + 1] = 0;
                }
            }
            const float4 z = make_float4(0.f, 0.f, 0.f, 0.f);
            #pragma unroll
            for (int m = 0; m < TM; m++)
                __stcs((float4*)out + (size_t)(slot0 + m) * HID4 + cb4, z);
            continue;
        }

        // --- phase A: metadata (lanes 0..7), same-tile prefetch, dup-ie ---
        if (lt < TM) {
            const int m = lt, t = t0 + m;
            int r0 = 0, r1 = 0, r2 = 0, r3 = 0, ord = 1, i0 = 0, i1 = 0;
            const bool pad = (t >= seq);
            if (!pad) {
                if (t < nn) {
                    int4 rr = ((const int4*)nodeData)[nOff + t];
                    r0 = rr.x; r1 = rr.y; r2 = rr.z; r3 = rr.w;
                    i0 = t; i1 = t; ord = 1;
                } else {
                    const int ge = eOff + (t - nn);
                    int4 rr = ((const int4*)edgeData)[ge];
                    r0 = rr.x; r1 = rr.y; r2 = rr.z; r3 = rr.w;
                    i0 = edgeIndex[ge]; i1 = edgeIndex[Etot + ge];
                    ord = (i0 == i1) ? 1 : 0;
                }
            }
            gMeta[m * 5 + 0] = r0; gMeta[m * 5 + 1] = r1;
            gMeta[m * 5 + 2] = r2; gMeta[m * 5 + 3] = r3;
            gMeta[m * 5 + 4] = ord;
            if (split == 0 && extraMode) {
                const int slot = slot0 + m;
                if (extraMode == 1) {
                    out[(size_t)F_ELEMS + slot] = pad ? 1.0f : 0.0f;
                    out[(size_t)F_ELEMS + M_ELEMS + 2 * slot]     = (float)i0;
                    out[(size_t)F_ELEMS + M_ELEMS + 2 * slot + 1] = (float)i1;
                } else {
                    ((unsigned char*)out)[(size_t)F_ELEMS * 4 + slot] = pad ? 1 : 0;
                    int* ip = (int*)((char*)out + (size_t)F_ELEMS * 4 + M_ELEMS);
                    ip[2 * slot] = i0; ip[2 * slot + 1] = i1;
                }
            }
        }
        {
            // L2 prefetch (same-tile, proven): thread (m = lt>>3, j = lt&7)
            // warms 128B line j of token m's 4 embed rows (this split's 1KB).
            const int m = lt >> 3, j = lt & 7;
            const int t = t0 + m;
            if (t < seq) {
                int4 rr;
                if (t < nn) rr = ((const int4*)nodeData)[nOff + t];
                else        rr = ((const int4*)edgeData)[eOff + (t - nn)];
                const char* eb = (const char*)embedW + (size_t)split * 1024 + j * 128;
                pf_l2(eb + (size_t)rr.x * 3072);
                pf_l2(eb + (size_t)rr.y * 3072);
                pf_l2(eb + (size_t)rr.z * 3072);
                pf_l2(eb + (size_t)rr.w * 3072);
            }
        }
        {
            // dup-ie: thread (m = lt&7, ko = lt>>3), kc = 8*ko: loads 8 k of
            // token m, writes 16 dup floats at stride-132 layout.
            // STS.128 banks within a phase: 132m mod 32 = 4m -> conflict-free.
            const int m  = lt & 7;
            const int kc = (lt >> 3) * 8;
            const int t = t0 + m;
            const bool pad = (t >= seq);
            int row = 0;
            if (!pad) {
                if (t < nn) row = nOff + t;
                else {
                    const int ge = eOff + (t - nn);
                    row = nOff + ((kc < 32) ? edgeIndex[ge] : edgeIndex[Etot + ge]);
                }
            }
            const float4* er4 = (const float4*)(eig + (size_t)row * 32 + (kc & 31));
            float4 v0, v1;
            if (pad) { v0 = make_float4(0,0,0,0); v1 = v0; }
            else     { v0 = er4[0]; v1 = er4[1]; }
            float4* dst = (float4*)(gIED + m * IESTRIDE + kc * 2);
            dst[0] = make_float4(v0.x, v0.x, v0.y, v0.y);
            dst[1] = make_float4(v0.z, v0.z, v0.w, v0.w);
            dst[2] = make_float4(v1.x, v1.x, v1.y, v1.y);
            dst[3] = make_float4(v1.z, v1.z, v1.w, v1.w);
        }
        asm volatile("bar.sync %0, %1;" :: "r"(barid), "r"(GSZ) : "memory");

        // --- phase B: GEMM ie[8][64] @ Wslice[64][256], MOV-free ---
        ull acc[TM][2];
        #pragma unroll
        for (int m = 0; m < TM; m++) { acc[m][0] = 0ull; acc[m][1] = 0ull; }

        #pragma unroll 2
        for (int kq = 0; kq < 16; kq++) {
            float4 w0 = sW4[(4 * kq + 0) * SCOLS4 + lt];
            float4 w1 = sW4[(4 * kq + 1) * SCOLS4 + lt];
            float4 w2 = sW4[(4 * kq + 2) * SCOLS4 + lt];
            float4 w3 = sW4[(4 * kq + 3) * SCOLS4 + lt];
            #pragma unroll
            for (int m = 0; m < TM; m++) {
                const ulonglong2* dp =
                    (const ulonglong2*)(gIED + m * IESTRIDE + 8 * kq);
                const ulonglong2 d01 = dp[0];   // dup(x0), dup(x1) — broadcast
                const ulonglong2 d23 = dp[1];   // dup(x2), dup(x3)
                fma2(acc[m][0], d01.x, lo2(w0)); fma2(acc[m][1], d01.x, hi2(w0));
                fma2(acc[m][0], d01.y, lo2(w1)); fma2(acc[m][1], d01.y, hi2(w1));
                fma2(acc[m][0], d23.x, lo2(w2)); fma2(acc[m][1], d23.x, hi2(w2));
                fma2(acc[m][0], d23.y, lo2(w3)); fma2(acc[m][1], d23.y, hi2(w3));
            }
        }

        // --- phase C: embed gather (L2-hot) + order + store, 128-bit ---
        const float4* em4 = (const float4*)embedW;
        const float4* ow4 = (const float4*)orderW;
        #pragma unroll
        for (int m = 0; m < TM; m++) {
            const int t = t0 + m;
            float4* o4 = (float4*)out + (size_t)(slot0 + m) * HID4 + cb4;
            if (t >= seq) {
                __stcs(o4, make_float4(0.f, 0.f, 0.f, 0.f));
            } else {
                const int r0 = gMeta[m * 5 + 0], r1 = gMeta[m * 5 + 1];
                const int r2 = gMeta[m * 5 + 2], r3 = gMeta[m * 5 + 3];
                const int ord = gMeta[m * 5 + 4];
                const float4 e0 = em4[(size_t)r0 * HID4 + cb4];
                const float4 e1 = em4[(size_t)r1 * HID4 + cb4];
                const float4 e2 = em4[(size_t)r2 * HID4 + cb4];
                const float4 e3 = em4[(size_t)r3 * HID4 + cb4];
                const float4 w  = ow4[(size_t)ord * HID4 + cb4];
                const float2 a0 = unpack2(acc[m][0]);
                const float2 a1 = unpack2(acc[m][1]);
                float4 v;
                v.x = a0.x + e0.x + e1.x + e2.x + e3.x + w.x;
                v.y = a0.y + e0.y + e1.y + e2.y + e3.y + w.y;
                v.z = a1.x + e0.z + e1.z + e2.z + e3.z + w.z;
                v.w = a1.y + e0.w + e1.w + e2.w + e3.w + w.w;
                __stcs(o4, v);
            }
        }
        asm volatile("bar.sync %0, %1;" :: "r"(barid), "r"(GSZ) : "memory");
    }
}

extern "C" void kernel_launch(void* const* d_in, const int* in_sizes, int n_in,
                              void* d_out, int out_size)
{
    const float* embedW   = (const float*)d_in[0];
    const float* lapW     = (const float*)d_in[1];
    const float* orderW   = (const float*)d_in[2];
    const float* eig      = (const float*)d_in[3];
    const int*   nodeData = (const int*)d_in[4];
    const int*   edgeData = (const int*)d_in[5];
    const int*   edgeIdx  = (const int*)d_in[6];
    const int*   nodeNum  = (const int*)d_in[7];
    const int*   edgeNum  = (const int*)d_in[8];

    const int Etot = in_sizes[6] / 2;

    int extraMode = 0;
    const long long allF  = (long long)F_ELEMS + M_ELEMS + I_ELEMS;           // 94740480
    const long long rawB  = (long long)F_ELEMS + (M_ELEMS + I_ELEMS * 4) / 4; // 94648320
    if ((long long)out_size == allF)      extraMode = 1;
    else if ((long long)out_size == rawB) extraMode = 2;

    cudaFuncSetAttribute(gft_kernel, cudaFuncAttributeMaxDynamicSharedMemorySize, SMEM_BYTES);
    gft_kernel<<<NWORK * NSPLIT, TPB, SMEM_BYTES>>>(embedW, lapW, orderW, eig,
                                                    nodeData, edgeData, edgeIdx,
                                                    nodeNum, edgeNum,
                                                    (float*)d_out, Etot, extraMode);
}

// round 12
// speedup vs baseline: 1.0884x; 1.0884x over previous
#include <cuda_runtime.h>
#include <string.h>

// ---------------------------------------------------------------------------
// GraphFeatureTokenizer fused kernel for GB300 (sm_103a) — Round 11
//
// Base = R3 (best, 307.7us): NSPLIT=3 x 256 cols, TM=8, 3 CTAs/SM (24 warps),
// fma.rn.f32x2 GEMM, same-tile L2 prefetch, __stcs streaming output.
// R11 single change: phase-A prefetches use prefetch.global.L2::evict_last.
// R9 proved hinting the DEMAND load is useless (the prefetch inserts the
// line with default policy first). Hinting the PREFETCH changes the
// insertion class: the 154MB embed table is retained against the 378MB
// evict-first output stream, cutting the measured ~45% demand-miss/churn.
// ---------------------------------------------------------------------------

#define HID      768
#define HID4     192              // float4 per row
#define NSPLIT   3
#define SCOLS4   64               // float4 cols per split
#define MAXLEN   15360
#define NB       8
#define SLOTS    (NB * MAXLEN)    // 122880
#define TM       8
#define NTILES   (SLOTS / TM)     // 15360
#define TPB      256
#define NGRP     4
#define GSZ      64
#define NWORK    152

#define F_ELEMS  (SLOTS * HID)    // 94371840
#define M_ELEMS  (SLOTS)          // 122880
#define I_ELEMS  (SLOTS * 2)     // 245760

#define SM_W_FLOATS   (64 * 256)              // 16384 floats = 64KB
#define SM_IE_FLOATS  (NGRP * TM * 64)        // 2048
#define SM_META_INTS  (NGRP * TM * 5)         // 160
#define SM_OFF_INTS   32
#define SMEM_BYTES    ((SM_W_FLOATS + SM_IE_FLOATS) * 4 + (SM_META_INTS + SM_OFF_INTS) * 4)

typedef unsigned long long ull;

__device__ __forceinline__ ull pack2(float x) {
    float2 q = make_float2(x, x);
    ull r; memcpy(&r, &q, 8);
    return r;
}
__device__ __forceinline__ float2 unpack2(ull v) {
    float2 r; memcpy(&r, &v, 8);
    return r;
}
__device__ __forceinline__ ull lo2(float4 w) {
    float2 q = make_float2(w.x, w.y);
    ull r; memcpy(&r, &q, 8);
    return r;
}
__device__ __forceinline__ ull hi2(float4 w) {
    float2 q = make_float2(w.z, w.w);
    ull r; memcpy(&r, &q, 8);
    return r;
}
__device__ __forceinline__ void fma2(ull& acc, ull a, ull b) {
    asm("fma.rn.f32x2 %0, %1, %2, %0;" : "+l"(acc) : "l"(a), "l"(b));
}
// prefetch that INSERTS the line with evict_last retention priority
__device__ __forceinline__ void pf_l2_el(const void* p) {
    asm volatile("prefetch.global.L2::evict_last [%0];" :: "l"(p));
}

extern "C" __global__ void __launch_bounds__(TPB, 3)
gft_kernel(const float* __restrict__ embedW,
           const float* __restrict__ lapW,
           const float* __restrict__ orderW,
           const float* __restrict__ eig,
           const int*   __restrict__ nodeData,
           const int*   __restrict__ edgeData,
           const int*   __restrict__ edgeIndex,
           const int*   __restrict__ nodeNum,
           const int*   __restrict__ edgeNum,
           float*       __restrict__ out,
           int Etot, int extraMode)
{
    extern __shared__ float smem[];
    float4* sW4   = (float4*)smem;                        // [64 k][64 c4]
    float*  sIE   = smem + SM_W_FLOATS;                   // [NGRP][TM][64]
    int*    sMeta = (int*)(sIE + SM_IE_FLOATS);           // [NGRP][TM][5]
    int*    sOff  = sMeta + SM_META_INTS;                 // [32]

    const int tid    = threadIdx.x;
    const int nwork  = gridDim.x / NSPLIT;
    const int split  = blockIdx.x / nwork;                // 0..2
    const int worker = blockIdx.x - split * nwork;

    // --- init: weight slice -> smem, prefix sums ---
    {
        const float4* s = (const float4*)lapW;
        #pragma unroll 4
        for (int i = tid; i < 64 * SCOLS4; i += TPB) {
            const int k = i >> 6, c4 = i & 63;
            sW4[i] = s[k * HID4 + split * SCOLS4 + c4];
        }
    }
    if (tid < NB) {
        int no = 0, eo = 0;
        for (int x = 0; x < tid; x++) { no += nodeNum[x]; eo += edgeNum[x]; }
        sOff[tid]      = no;
        sOff[8 + tid]  = eo;
        sOff[16 + tid] = nodeNum[tid];
        sOff[24 + tid] = nodeNum[tid] + edgeNum[tid];
    }
    __syncthreads();

    const int g  = tid >> 6;
    const int lt = tid & 63;
    float* gIE   = sIE + g * TM * 64;
    int*   gMeta = sMeta + g * TM * 5;
    const int barid = 1 + g;
    const int grp   = worker * NGRP + g;
    const int ngrp  = nwork * NGRP;
    const int cb4   = split * SCOLS4 + lt;                // thread's float4 col

    for (int tile = grp; tile < NTILES; tile += ngrp) {
        const int slot0 = tile * TM;
        const int b  = slot0 / MAXLEN;
        const int t0 = slot0 - b * MAXLEN;
        const int nOff = sOff[b], eOff = sOff[8 + b];
        const int nn = sOff[16 + b], seq = sOff[24 + b];

        if (t0 >= seq) {
            if (split == 0 && lt < TM && extraMode) {
                const int slot = slot0 + lt;
                if (extraMode == 1) {
                    out[(size_t)F_ELEMS + slot] = 1.0f;
                    out[(size_t)F_ELEMS + M_ELEMS + 2 * slot]     = 0.0f;
                    out[(size_t)F_ELEMS + M_ELEMS + 2 * slot + 1] = 0.0f;
                } else {
                    ((unsigned char*)out)[(size_t)F_ELEMS * 4 + slot] = 1;
                    int* ip = (int*)((char*)out + (size_t)F_ELEMS * 4 + M_ELEMS);
                    ip[2 * slot] = 0; ip[2 * slot + 1] = 0;
                }
            }
            const float4 z = make_float4(0.f, 0.f, 0.f, 0.f);
            #pragma unroll
            for (int m = 0; m < TM; m++)
                __stcs((float4*)out + (size_t)(slot0 + m) * HID4 + cb4, z);
            continue;
        }

        // --- phase A: metadata (lanes 0..7), evict_last prefetch, ie ---
        if (lt < TM) {
            const int m = lt, t = t0 + m;
            int r0 = 0, r1 = 0, r2 = 0, r3 = 0, ord = 1, i0 = 0, i1 = 0;
            const bool pad = (t >= seq);
            if (!pad) {
                if (t < nn) {
                    int4 rr = ((const int4*)nodeData)[nOff + t];
                    r0 = rr.x; r1 = rr.y; r2 = rr.z; r3 = rr.w;
                    i0 = t; i1 = t; ord = 1;
                } else {
                    const int ge = eOff + (t - nn);
                    int4 rr = ((const int4*)edgeData)[ge];
                    r0 = rr.x; r1 = rr.y; r2 = rr.z; r3 = rr.w;
                    i0 = edgeIndex[ge]; i1 = edgeIndex[Etot + ge];
                    ord = (i0 == i1) ? 1 : 0;
                }
            }
            gMeta[m * 5 + 0] = r0; gMeta[m * 5 + 1] = r1;
            gMeta[m * 5 + 2] = r2; gMeta[m * 5 + 3] = r3;
            gMeta[m * 5 + 4] = ord;
            if (split == 0 && extraMode) {
                const int slot = slot0 + m;
                if (extraMode == 1) {
                    out[(size_t)F_ELEMS + slot] = pad ? 1.0f : 0.0f;
                    out[(size_t)F_ELEMS + M_ELEMS + 2 * slot]     = (float)i0;
                    out[(size_t)F_ELEMS + M_ELEMS + 2 * slot + 1] = (float)i1;
                } else {
                    ((unsigned char*)out)[(size_t)F_ELEMS * 4 + slot] = pad ? 1 : 0;
                    int* ip = (int*)((char*)out + (size_t)F_ELEMS * 4 + M_ELEMS);
                    ip[2 * slot] = i0; ip[2 * slot + 1] = i1;
                }
            }
        }
        {
            // L2 prefetch with evict_last insertion: thread (m = lt>>3,
            // j = lt&7) warms line j of token m's 4 embed rows (1KB slice).
            const int m = lt >> 3, j = lt & 7;
            const int t = t0 + m;
            if (t < seq) {
                int4 rr;
                if (t < nn) rr = ((const int4*)nodeData)[nOff + t];
                else        rr = ((const int4*)edgeData)[eOff + (t - nn)];
                const char* eb = (const char*)embedW + (size_t)split * 1024 + j * 128;
                pf_l2_el(eb + (size_t)rr.x * 3072);
                pf_l2_el(eb + (size_t)rr.y * 3072);
                pf_l2_el(eb + (size_t)rr.z * 3072);
                pf_l2_el(eb + (size_t)rr.w * 3072);
            }
        }
        {
            // ie gather: thread fills 8 consecutive j's of one token's ie[64]
            const int m = lt >> 3;
            const int jbase = (lt & 7) * 8;
            const int t = t0 + m;
            const bool pad = (t >= seq);
            int row = 0;
            if (!pad) {
                if (t < nn) row = nOff + t;
                else {
                    const int ge = eOff + (t - nn);
                    row = nOff + ((jbase < 32) ? edgeIndex[ge] : edgeIndex[Etot + ge]);
                }
            }
            const int jj = jbase & 31;
            const float4* er4 = (const float4*)(eig + (size_t)row * 32 + jj);
            float4 v0, v1;
            if (pad) { v0 = make_float4(0,0,0,0); v1 = v0; }
            else     { v0 = er4[0]; v1 = er4[1]; }
            float4* dst = (float4*)(gIE + m * 64 + jbase);
            dst[0] = v0; dst[1] = v1;
        }
        asm volatile("bar.sync %0, %1;" :: "r"(barid), "r"(GSZ) : "memory");

        // --- phase B: GEMM ie[8][64] @ Wslice[64][256], 128-bit LDS ---
        ull acc[TM][2];
        #pragma unroll
        for (int m = 0; m < TM; m++) { acc[m][0] = 0ull; acc[m][1] = 0ull; }

        #pragma unroll 2
        for (int kq = 0; kq < 16; kq++) {
            float4 w0 = sW4[(4 * kq + 0) * SCOLS4 + lt];
            float4 w1 = sW4[(4 * kq + 1) * SCOLS4 + lt];
            float4 w2 = sW4[(4 * kq + 2) * SCOLS4 + lt];
            float4 w3 = sW4[(4 * kq + 3) * SCOLS4 + lt];
            const ull w0l = lo2(w0), w0h = hi2(w0);
            const ull w1l = lo2(w1), w1h = hi2(w1);
            const ull w2l = lo2(w2), w2h = hi2(w2);
            const ull w3l = lo2(w3), w3h = hi2(w3);
            #pragma unroll
            for (int m = 0; m < TM; m++) {
                const float4 p = ((const float4*)(gIE + m * 64))[kq];
                const ull x0 = pack2(p.x), x1 = pack2(p.y);
                const ull x2 = pack2(p.z), x3 = pack2(p.w);
                fma2(acc[m][0], x0, w0l); fma2(acc[m][1], x0, w0h);
                fma2(acc[m][0], x1, w1l); fma2(acc[m][1], x1, w1h);
                fma2(acc[m][0], x2, w2l); fma2(acc[m][1], x2, w2h);
                fma2(acc[m][0], x3, w3l); fma2(acc[m][1], x3, w3h);
            }
        }

        // --- phase C: embed gather (L2-hot) + order + store, 128-bit ---
        const float4* em4 = (const float4*)embedW;
        const float4* ow4 = (const float4*)orderW;
        #pragma unroll
        for (int m = 0; m < TM; m++) {
            const int t = t0 + m;
            float4* o4 = (float4*)out + (size_t)(slot0 + m) * HID4 + cb4;
            if (t >= seq) {
                __stcs(o4, make_float4(0.f, 0.f, 0.f, 0.f));
            } else {
                const int r0 = gMeta[m * 5 + 0], r1 = gMeta[m * 5 + 1];
                const int r2 = gMeta[m * 5 + 2], r3 = gMeta[m * 5 + 3];
                const int ord = gMeta[m * 5 + 4];
                const float4 e0 = em4[(size_t)r0 * HID4 + cb4];
                const float4 e1 = em4[(size_t)r1 * HID4 + cb4];
                const float4 e2 = em4[(size_t)r2 * HID4 + cb4];
                const float4 e3 = em4[(size_t)r3 * HID4 + cb4];
                const float4 w  = ow4[(size_t)ord * HID4 + cb4];
                const float2 a0 = unpack2(acc[m][0]);
                const float2 a1 = unpack2(acc[m][1]);
                float4 v;
                v.x = a0.x + e0.x + e1.x + e2.x + e3.x + w.x;
                v.y = a0.y + e0.y + e1.y + e2.y + e3.y + w.y;
                v.z = a1.x + e0.z + e1.z + e2.z + e3.z + w.z;
                v.w = a1.y + e0.w + e1.w + e2.w + e3.w + w.w;
                __stcs(o4, v);
            }
        }
        asm volatile("bar.sync %0, %1;" :: "r"(barid), "r"(GSZ) : "memory");
    }
}

extern "C" void kernel_launch(void* const* d_in, const int* in_sizes, int n_in,
                              void* d_out, int out_size)
{
    const float* embedW   = (const float*)d_in[0];
    const float* lapW     = (const float*)d_in[1];
    const float* orderW   = (const float*)d_in[2];
    const float* eig      = (const float*)d_in[3];
    const int*   nodeData = (const int*)d_in[4];
    const int*   edgeData = (const int*)d_in[5];
    const int*   edgeIdx  = (const int*)d_in[6];
    const int*   nodeNum  = (const int*)d_in[7];
    const int*   edgeNum  = (const int*)d_in[8];

    const int Etot = in_sizes[6] / 2;

    int extraMode = 0;
    const long long allF  = (long long)F_ELEMS + M_ELEMS + I_ELEMS;           // 94740480
    const long long rawB  = (long long)F_ELEMS + (M_ELEMS + I_ELEMS * 4) / 4; // 94648320
    if ((long long)out_size == allF)      extraMode = 1;
    else if ((long long)out_size == rawB) extraMode = 2;

    cudaFuncSetAttribute(gft_kernel, cudaFuncAttributeMaxDynamicSharedMemorySize, SMEM_BYTES);
    gft_kernel<<<NWORK * NSPLIT, TPB, SMEM_BYTES>>>(embedW, lapW, orderW, eig,
                                                    nodeData, edgeData, edgeIdx,
                                                    nodeNum, edgeNum,
                                                    (float*)d_out, Etot, extraMode);
}

// round 17
// speedup vs baseline: 1.1391x; 1.0466x over previous
#include <cuda_runtime.h>
#include <string.h>

// ---------------------------------------------------------------------------
// GraphFeatureTokenizer fused kernel for GB300 (sm_103a) — Round 15
//
// Goal unchanged from R12/R14 (both lost to infra failures on TPB=320):
// occupancy is REGISTER-bound (80 regs -> 24 warps/SM at best-known 307us).
// Route B via an infra-proven config family: TPB=512, __launch_bounds__(512,2)
// -> 1024 thr/SM at <=64 regs (R7 compiled this exact GEMM loop at 64 regs)
// -> 32 warps/SM. smem/CTA ~81.4KB <= 114KB at 2 CTAs (comfortable).
// All else identical to the 307us kernel: NSPLIT=3 x 256 cols, TM=8,
// 64-thread groups + named barriers, same-tile evict_last prefetch,
// fma.rn.f32x2 GEMM, __stcs streaming output.
// ---------------------------------------------------------------------------

#define HID      768
#define HID4     192              // float4 per row
#define NSPLIT   3
#define SCOLS4   64               // float4 cols per split
#define MAXLEN   15360
#define NB       8
#define SLOTS    (NB * MAXLEN)    // 122880
#define TM       8
#define NTILES   (SLOTS / TM)     // 15360
#define TPB      512
#define NGRP     8                // 8 groups of 64 threads
#define GSZ      64
#define NWORK    101              // 2 CTAs/SM * 152 SMs ~ 304 -> 3*101 = 303

#define F_ELEMS  (SLOTS * HID)    // 94371840
#define M_ELEMS  (SLOTS)          // 122880
#define I_ELEMS  (SLOTS * 2)      // 245760

#define SM_W_FLOATS   (64 * 256)              // 16384 floats = 64KB
#define SM_IE_FLOATS  (NGRP * TM * 64)        // 4096 floats = 16KB
#define SM_META_INTS  (NGRP * TM * 5)         // 320
#define SM_OFF_INTS   32
#define SMEM_BYTES    ((SM_W_FLOATS + SM_IE_FLOATS) * 4 + (SM_META_INTS + SM_OFF_INTS) * 4)

typedef unsigned long long ull;

__device__ __forceinline__ ull pack2(float x) {
    float2 q = make_float2(x, x);
    ull r; memcpy(&r, &q, 8);
    return r;
}
__device__ __forceinline__ float2 unpack2(ull v) {
    float2 r; memcpy(&r, &v, 8);
    return r;
}
__device__ __forceinline__ ull lo2(float4 w) {
    float2 q = make_float2(w.x, w.y);
    ull r; memcpy(&r, &q, 8);
    return r;
}
__device__ __forceinline__ ull hi2(float4 w) {
    float2 q = make_float2(w.z, w.w);
    ull r; memcpy(&r, &q, 8);
    return r;
}
__device__ __forceinline__ void fma2(ull& acc, ull a, ull b) {
    asm("fma.rn.f32x2 %0, %1, %2, %0;" : "+l"(acc) : "l"(a), "l"(b));
}
__device__ __forceinline__ void pf_l2_el(const void* p) {
    asm volatile("prefetch.global.L2::evict_last [%0];" :: "l"(p));
}

extern "C" __global__ void __launch_bounds__(TPB, 2)
gft_kernel(const float* __restrict__ embedW,
           const float* __restrict__ lapW,
           const float* __restrict__ orderW,
           const float* __restrict__ eig,
           const int*   __restrict__ nodeData,
           const int*   __restrict__ edgeData,
           const int*   __restrict__ edgeIndex,
           const int*   __restrict__ nodeNum,
           const int*   __restrict__ edgeNum,
           float*       __restrict__ out,
           int Etot, int extraMode)
{
    extern __shared__ float smem[];
    float4* sW4   = (float4*)smem;                        // [64 k][64 c4]
    float*  sIE   = smem + SM_W_FLOATS;                   // [NGRP][TM][64]
    int*    sMeta = (int*)(sIE + SM_IE_FLOATS);           // [NGRP][TM][5]
    int*    sOff  = sMeta + SM_META_INTS;                 // [32]

    const int tid    = threadIdx.x;
    const int nwork  = gridDim.x / NSPLIT;
    const int split  = blockIdx.x / nwork;                // 0..2
    const int worker = blockIdx.x - split * nwork;

    // --- init: weight slice -> smem, prefix sums ---
    {
        const float4* s = (const float4*)lapW;
        #pragma unroll 4
        for (int i = tid; i < 64 * SCOLS4; i += TPB) {
            const int k = i >> 6, c4 = i & 63;
            sW4[i] = s[k * HID4 + split * SCOLS4 + c4];
        }
    }
    if (tid < NB) {
        int no = 0, eo = 0;
        for (int x = 0; x < tid; x++) { no += nodeNum[x]; eo += edgeNum[x]; }
        sOff[tid]      = no;
        sOff[8 + tid]  = eo;
        sOff[16 + tid] = nodeNum[tid];
        sOff[24 + tid] = nodeNum[tid] + edgeNum[tid];
    }
    __syncthreads();

    const int g  = tid >> 6;                 // group 0..7
    const int lt = tid & 63;
    float* gIE   = sIE + g * TM * 64;
    int*   gMeta = sMeta + g * TM * 5;
    const int barid = 1 + g;                 // named barriers 1..8 (of 16)
    const int grp   = worker * NGRP + g;
    const int ngrp  = nwork * NGRP;
    const int cb4   = split * SCOLS4 + lt;   // thread's float4 col

    for (int tile = grp; tile < NTILES; tile += ngrp) {
        const int slot0 = tile * TM;
        const int b  = slot0 / MAXLEN;
        const int t0 = slot0 - b * MAXLEN;
        const int nOff = sOff[b], eOff = sOff[8 + b];
        const int nn = sOff[16 + b], seq = sOff[24 + b];

        if (t0 >= seq) {
            if (split == 0 && lt < TM && extraMode) {
                const int slot = slot0 + lt;
                if (extraMode == 1) {
                    out[(size_t)F_ELEMS + slot] = 1.0f;
                    out[(size_t)F_ELEMS + M_ELEMS + 2 * slot]     = 0.0f;
                    out[(size_t)F_ELEMS + M_ELEMS + 2 * slot + 1] = 0.0f;
                } else {
                    ((unsigned char*)out)[(size_t)F_ELEMS * 4 + slot] = 1;
                    int* ip = (int*)((char*)out + (size_t)F_ELEMS * 4 + M_ELEMS);
                    ip[2 * slot] = 0; ip[2 * slot + 1] = 0;
                }
            }
            const float4 z = make_float4(0.f, 0.f, 0.f, 0.f);
            #pragma unroll
            for (int m = 0; m < TM; m++)
                __stcs((float4*)out + (size_t)(slot0 + m) * HID4 + cb4, z);
            continue;
        }

        // --- phase A: metadata (lanes 0..7), evict_last prefetch, ie ---
        if (lt < TM) {
            const int m = lt, t = t0 + m;
            int r0 = 0, r1 = 0, r2 = 0, r3 = 0, ord = 1, i0 = 0, i1 = 0;
            const bool pad = (t >= seq);
            if (!pad) {
                if (t < nn) {
                    int4 rr = ((const int4*)nodeData)[nOff + t];
                    r0 = rr.x; r1 = rr.y; r2 = rr.z; r3 = rr.w;
                    i0 = t; i1 = t; ord = 1;
                } else {
                    const int ge = eOff + (t - nn);
                    int4 rr = ((const int4*)edgeData)[ge];
                    r0 = rr.x; r1 = rr.y; r2 = rr.z; r3 = rr.w;
                    i0 = edgeIndex[ge]; i1 = edgeIndex[Etot + ge];
                    ord = (i0 == i1) ? 1 : 0;
                }
            }
            gMeta[m * 5 + 0] = r0; gMeta[m * 5 + 1] = r1;
            gMeta[m * 5 + 2] = r2; gMeta[m * 5 + 3] = r3;
            gMeta[m * 5 + 4] = ord;
            if (split == 0 && extraMode) {
                const int slot = slot0 + m;
                if (extraMode == 1) {
                    out[(size_t)F_ELEMS + slot] = pad ? 1.0f : 0.0f;
                    out[(size_t)F_ELEMS + M_ELEMS + 2 * slot]     = (float)i0;
                    out[(size_t)F_ELEMS + M_ELEMS + 2 * slot + 1] = (float)i1;
                } else {
                    ((unsigned char*)out)[(size_t)F_ELEMS * 4 + slot] = pad ? 1 : 0;
                    int* ip = (int*)((char*)out + (size_t)F_ELEMS * 4 + M_ELEMS);
                    ip[2 * slot] = i0; ip[2 * slot + 1] = i1;
                }
            }
        }
        {
            // L2 prefetch (same-tile distance, evict_last insertion):
            // thread (m = lt>>3, j = lt&7): line j of token m's 4 rows.
            const int m = lt >> 3, j = lt & 7;
            const int t = t0 + m;
            if (t < seq) {
                int4 rr;
                if (t < nn) rr = ((const int4*)nodeData)[nOff + t];
                else        rr = ((const int4*)edgeData)[eOff + (t - nn)];
                const char* eb = (const char*)embedW + (size_t)split * 1024 + j * 128;
                pf_l2_el(eb + (size_t)rr.x * 3072);
                pf_l2_el(eb + (size_t)rr.y * 3072);
                pf_l2_el(eb + (size_t)rr.z * 3072);
                pf_l2_el(eb + (size_t)rr.w * 3072);
            }
        }
        {
            // ie gather: thread fills 8 consecutive j's of one token's ie[64]
            const int m = lt >> 3;
            const int jbase = (lt & 7) * 8;
            const int t = t0 + m;
            const bool pad = (t >= seq);
            int row = 0;
            if (!pad) {
                if (t < nn) row = nOff + t;
                else {
                    const int ge = eOff + (t - nn);
                    row = nOff + ((jbase < 32) ? edgeIndex[ge] : edgeIndex[Etot + ge]);
                }
            }
            const int jj = jbase & 31;
            const float4* er4 = (const float4*)(eig + (size_t)row * 32 + jj);
            float4 v0, v1;
            if (pad) { v0 = make_float4(0,0,0,0); v1 = v0; }
            else     { v0 = er4[0]; v1 = er4[1]; }
            float4* dst = (float4*)(gIE + m * 64 + jbase);
            dst[0] = v0; dst[1] = v1;
        }
        asm volatile("bar.sync %0, %1;" :: "r"(barid), "r"(GSZ) : "memory");

        // --- phase B: GEMM ie[8][64] @ Wslice[64][256], 128-bit LDS ---
        ull acc[TM][2];
        #pragma unroll
        for (int m = 0; m < TM; m++) { acc[m][0] = 0ull; acc[m][1] = 0ull; }

        #pragma unroll 2
        for (int kq = 0; kq < 16; kq++) {
            float4 w0 = sW4[(4 * kq + 0) * SCOLS4 + lt];
            float4 w1 = sW4[(4 * kq + 1) * SCOLS4 + lt];
            float4 w2 = sW4[(4 * kq + 2) * SCOLS4 + lt];
            float4 w3 = sW4[(4 * kq + 3) * SCOLS4 + lt];
            const ull w0l = lo2(w0), w0h = hi2(w0);
            const ull w1l = lo2(w1), w1h = hi2(w1);
            const ull w2l = lo2(w2), w2h = hi2(w2);
            const ull w3l = lo2(w3), w3h = hi2(w3);
            #pragma unroll
            for (int m = 0; m < TM; m++) {
                const float4 p = ((const float4*)(gIE + m * 64))[kq];
                const ull x0 = pack2(p.x), x1 = pack2(p.y);
                const ull x2 = pack2(p.z), x3 = pack2(p.w);
                fma2(acc[m][0], x0, w0l); fma2(acc[m][1], x0, w0h);
                fma2(acc[m][0], x1, w1l); fma2(acc[m][1], x1, w1h);
                fma2(acc[m][0], x2, w2l); fma2(acc[m][1], x2, w2h);
                fma2(acc[m][0], x3, w3l); fma2(acc[m][1], x3, w3h);
            }
        }

        // --- phase C: embed gather (L2-hot) + order + store, 128-bit ---
        const float4* em4 = (const float4*)embedW;
        const float4* ow4 = (const float4*)orderW;
        #pragma unroll
        for (int m = 0; m < TM; m++) {
            const int t = t0 + m;
            float4* o4 = (float4*)out + (size_t)(slot0 + m) * HID4 + cb4;
            if (t >= seq) {
                __stcs(o4, make_float4(0.f, 0.f, 0.f, 0.f));
            } else {
                const int r0 = gMeta[m * 5 + 0], r1 = gMeta[m * 5 + 1];
                const int r2 = gMeta[m * 5 + 2], r3 = gMeta[m * 5 + 3];
                const int ord = gMeta[m * 5 + 4];
                const float4 e0 = em4[(size_t)r0 * HID4 + cb4];
                const float4 e1 = em4[(size_t)r1 * HID4 + cb4];
                const float4 e2 = em4[(size_t)r2 * HID4 + cb4];
                const float4 e3 = em4[(size_t)r3 * HID4 + cb4];
                const float4 w  = ow4[(size_t)ord * HID4 + cb4];
                const float2 a0 = unpack2(acc[m][0]);
                const float2 a1 = unpack2(acc[m][1]);
                float4 v;
                v.x = a0.x + e0.x + e1.x + e2.x + e3.x + w.x;
                v.y = a0.y + e0.y + e1.y + e2.y + e3.y + w.y;
                v.z = a1.x + e0.z + e1.z + e2.z + e3.z + w.z;
                v.w = a1.y + e0.w + e1.w + e2.w + e3.w + w.w;
                __stcs(o4, v);
            }
        }
        asm volatile("bar.sync %0, %1;" :: "r"(barid), "r"(GSZ) : "memory");
    }
}

extern "C" void kernel_launch(void* const* d_in, const int* in_sizes, int n_in,
                              void* d_out, int out_size)
{
    const float* embedW   = (const float*)d_in[0];
    const float* lapW     = (const float*)d_in[1];
    const float* orderW   = (const float*)d_in[2];
    const float* eig      = (const float*)d_in[3];
    const int*   nodeData = (const int*)d_in[4];
    const int*   edgeData = (const int*)d_in[5];
    const int*   edgeIdx  = (const int*)d_in[6];
    const int*   nodeNum  = (const int*)d_in[7];
    const int*   edgeNum  = (const int*)d_in[8];

    const int Etot = in_sizes[6] / 2;

    int extraMode = 0;
    const long long allF  = (long long)F_ELEMS + M_ELEMS + I_ELEMS;           // 94740480
    const long long rawB  = (long long)F_ELEMS + (M_ELEMS + I_ELEMS * 4) / 4; // 94648320
    if ((long long)out_size == allF)      extraMode = 1;
    else if ((long long)out_size == rawB) extraMode = 2;

    cudaFuncSetAttribute(gft_kernel, cudaFuncAttributeMaxDynamicSharedMemorySize, SMEM_BYTES);
    gft_kernel<<<NWORK * NSPLIT, TPB, SMEM_BYTES>>>(embedW, lapW, orderW, eig,
                                                    nodeData, edgeData, edgeIdx,
                                                    nodeNum, edgeNum,
                                                    (float*)d_out, Etot, extraMode);
}